// round 3
// baseline (speedup 1.0000x reference)
#include <cuda_runtime.h>
#include <math.h>

// Problem constants
#define Bq   4
#define Sq   2048
#define Dm   1024
#define Hh   16
#define HDm  64
#define DFm  4096
#define NTOK (Bq*Sq)   // 8192

// Scratch (module-load allocated, not runtime allocation)
__device__ float g_xn [NTOK*Dm];
__device__ float g_q  [NTOK*Dm];
__device__ float g_k  [NTOK*Dm];
__device__ float g_v  [NTOK*Dm];
__device__ float g_att[NTOK*Dm];
__device__ float g_x2 [NTOK*Dm];
__device__ float g_h  [NTOK*DFm];

// ---------------------------------------------------------------------------
// LayerNorm: one block per row of 1024, 256 threads, 1 float4/thread
// ---------------------------------------------------------------------------
__global__ __launch_bounds__(256)
void ln_kernel(const float* __restrict__ X, const float* __restrict__ G,
               const float* __restrict__ Bt, float* __restrict__ Y)
{
    __shared__ float ss[8], sq[8];
    const int r = blockIdx.x, tid = threadIdx.x;
    const float* xr = X + (size_t)r * Dm;
    float4 v = *(const float4*)(xr + tid * 4);
    float s = v.x + v.y + v.z + v.w;
    float q = v.x*v.x + v.y*v.y + v.z*v.z + v.w*v.w;
#pragma unroll
    for (int off = 16; off >= 1; off >>= 1) {
        s += __shfl_xor_sync(0xffffffffu, s, off);
        q += __shfl_xor_sync(0xffffffffu, q, off);
    }
    if ((tid & 31) == 0) { ss[tid >> 5] = s; sq[tid >> 5] = q; }
    __syncthreads();
    float ts = 0.f, tq = 0.f;
#pragma unroll
    for (int w = 0; w < 8; w++) { ts += ss[w]; tq += sq[w]; }
    const float mu   = ts * (1.0f / Dm);
    const float var  = tq * (1.0f / Dm) - mu * mu;
    const float rstd = rsqrtf(var + 1e-5f);
    float4 g4 = *(const float4*)(G  + tid * 4);
    float4 b4 = *(const float4*)(Bt + tid * 4);
    float4 o;
    o.x = (v.x - mu) * rstd * g4.x + b4.x;
    o.y = (v.y - mu) * rstd * g4.y + b4.y;
    o.z = (v.z - mu) * rstd * g4.z + b4.z;
    o.w = (v.w - mu) * rstd * g4.w + b4.w;
    *(float4*)(Y + (size_t)r * Dm + tid * 4) = o;
}

// ---------------------------------------------------------------------------
// SGEMM: C[M,N] = A[M,K] @ W[K,N] + bias, with epilogues.
// 128x128 tile, BK=16, 256 threads, 8x8 per thread, register double buffer.
// MODE: 0 = bias only, 1 = bias+GELU(exact), 2 = bias+residual, 3 = QKV scatter
// M=8192 always; M,N multiples of 128; K multiple of 16 -> no guards.
// ---------------------------------------------------------------------------
template<int MODE>
__global__ __launch_bounds__(256, 2)
void sgemm_kernel(const float* __restrict__ A, const float* __restrict__ Wt,
                  const float* __restrict__ bias, const float* __restrict__ res,
                  float* __restrict__ C, int N, int K)
{
    __shared__ float As[16][128];
    __shared__ float Bs[16][128];
    const int tid = threadIdx.x;
    const int tx = tid & 15, ty = tid >> 4;
    const int m0 = blockIdx.y * 128, n0 = blockIdx.x * 128;
    const float* Ab = A  + (size_t)m0 * K;
    const float* Bb = Wt + n0;

    float acc[8][8];
#pragma unroll
    for (int i = 0; i < 8; i++)
#pragma unroll
        for (int j = 0; j < 8; j++) acc[i][j] = 0.f;

    const int f2  = tid + 256;
    const int ra1 = tid >> 2,  ka1 = (tid & 3) * 4;
    const int ra2 = f2  >> 2,  ka2 = (f2  & 3) * 4;
    const int rb1 = tid >> 5,  nb1 = (tid & 31) * 4;
    const int rb2 = f2  >> 5,  nb2 = (f2  & 31) * 4;

    float4 pa0, pa1, pb0, pb1;
    // prologue: tile 0
    pa0 = *(const float4*)(Ab + (size_t)ra1 * K + ka1);
    pa1 = *(const float4*)(Ab + (size_t)ra2 * K + ka2);
    pb0 = *(const float4*)(Bb + (size_t)rb1 * N + nb1);
    pb1 = *(const float4*)(Bb + (size_t)rb2 * N + nb2);
    As[ka1+0][ra1] = pa0.x; As[ka1+1][ra1] = pa0.y; As[ka1+2][ra1] = pa0.z; As[ka1+3][ra1] = pa0.w;
    As[ka2+0][ra2] = pa1.x; As[ka2+1][ra2] = pa1.y; As[ka2+2][ra2] = pa1.z; As[ka2+3][ra2] = pa1.w;
    *(float4*)&Bs[rb1][nb1] = pb0;
    *(float4*)&Bs[rb2][nb2] = pb1;
    __syncthreads();

    const int ntiles = K >> 4;
    for (int kt = 0; kt < ntiles; kt++) {
        const int k0n = (kt + 1) << 4;
        if (kt + 1 < ntiles) {
            pa0 = *(const float4*)(Ab + (size_t)ra1 * K + k0n + ka1);
            pa1 = *(const float4*)(Ab + (size_t)ra2 * K + k0n + ka2);
            pb0 = *(const float4*)(Bb + (size_t)(k0n + rb1) * N + nb1);
            pb1 = *(const float4*)(Bb + (size_t)(k0n + rb2) * N + nb2);
        }
#pragma unroll
        for (int k = 0; k < 16; k++) {
            float a[8], b[8];
            float4 t;
            t = *(float4*)&As[k][ty*8];     a[0]=t.x; a[1]=t.y; a[2]=t.z; a[3]=t.w;
            t = *(float4*)&As[k][ty*8+4];   a[4]=t.x; a[5]=t.y; a[6]=t.z; a[7]=t.w;
            t = *(float4*)&Bs[k][tx*8];     b[0]=t.x; b[1]=t.y; b[2]=t.z; b[3]=t.w;
            t = *(float4*)&Bs[k][tx*8+4];   b[4]=t.x; b[5]=t.y; b[6]=t.z; b[7]=t.w;
#pragma unroll
            for (int i = 0; i < 8; i++)
#pragma unroll
                for (int j = 0; j < 8; j++)
                    acc[i][j] += a[i] * b[j];
        }
        __syncthreads();
        if (kt + 1 < ntiles) {
            As[ka1+0][ra1] = pa0.x; As[ka1+1][ra1] = pa0.y; As[ka1+2][ra1] = pa0.z; As[ka1+3][ra1] = pa0.w;
            As[ka2+0][ra2] = pa1.x; As[ka2+1][ra2] = pa1.y; As[ka2+2][ra2] = pa1.z; As[ka2+3][ra2] = pa1.w;
            *(float4*)&Bs[rb1][nb1] = pb0;
            *(float4*)&Bs[rb2][nb2] = pb1;
            __syncthreads();
        }
    }

    // epilogue
    float bb[8];
    *(float4*)&bb[0] = *(const float4*)(bias + n0 + tx*8);
    *(float4*)&bb[4] = *(const float4*)(bias + n0 + tx*8 + 4);

#pragma unroll
    for (int i = 0; i < 8; i++) {
        const int m = m0 + ty * 8 + i;
        if (MODE == 3) {
            const int b = m >> 11, s = m & 2047;   // S = 2048
#pragma unroll
            for (int jj = 0; jj < 8; jj += 4) {
                const int n = n0 + tx * 8 + jj;
                const int h = n >> 6, hd = n & 63;
                float4 o = make_float4(acc[i][jj+0] + bb[jj+0],
                                       acc[i][jj+1] + bb[jj+1],
                                       acc[i][jj+2] + bb[jj+2],
                                       acc[i][jj+3] + bb[jj+3]);
                *(float4*)(C + (((size_t)(b * Hh + h) * Sq + s) * HDm + hd)) = o;
            }
        } else {
            float* Crow = C + (size_t)m * N + n0 + tx * 8;
            const float* Rrow = (MODE == 2) ? (res + (size_t)m * N + n0 + tx * 8) : nullptr;
#pragma unroll
            for (int jj = 0; jj < 8; jj += 4) {
                float vv[4];
#pragma unroll
                for (int w = 0; w < 4; w++) vv[w] = acc[i][jj+w] + bb[jj+w];
                if (MODE == 1) {
#pragma unroll
                    for (int w = 0; w < 4; w++) vv[w] = vv[w] * normcdff(vv[w]);
                } else if (MODE == 2) {
                    float4 rv = *(const float4*)(Rrow + jj);
                    vv[0] += rv.x; vv[1] += rv.y; vv[2] += rv.z; vv[3] += rv.w;
                }
                *(float4*)(Crow + jj) = make_float4(vv[0], vv[1], vv[2], vv[3]);
            }
        }
    }
}

// ---------------------------------------------------------------------------
// Flash attention, fp32. One CTA = (one bh head, 64 queries). 256 threads,
// 4x4 outputs/thread. KV tiled by 64. Row softmax stats replicated across the
// 16 lanes sharing a row (shfl reductions), no smem stats needed.
// Q/K/V layout: [B*H, S, 64]. Output written to [B, S, D] token-major.
// ---------------------------------------------------------------------------
#define AP 68   // padded row stride in floats
#define ATT_SMEM (4 * 64 * AP * 4)

__global__ __launch_bounds__(256, 2)
void attn_kernel(const float* __restrict__ Qg, const float* __restrict__ Kg,
                 const float* __restrict__ Vg, float* __restrict__ Og)
{
    extern __shared__ float sm[];
    float* qs  = sm;              // [64][AP]  row=q,   col=hd  (pre-scaled)
    float* kst = sm + 64*AP;      // [64][AP]  row=hd,  col=kcol (transposed K)
    float* vs  = sm + 2*64*AP;    // [64][AP]  row=kk,  col=hd
    float* ps  = sm + 3*64*AP;    // [64][AP]  row=q,   col=kcol

    const int tid = threadIdx.x;
    const int tx = tid & 15, ty = tid >> 4;
    const int bh = blockIdx.y;
    const int q0 = blockIdx.x * 64;
    const float* Qb = Qg + ((size_t)bh * Sq + q0) * HDm;
    const float* Kb = Kg + (size_t)bh * Sq * HDm;
    const float* Vb = Vg + (size_t)bh * Sq * HDm;

    // load Q tile, pre-scaled by 1/sqrt(64)
#pragma unroll
    for (int u = 0; u < 4; u++) {
        const int f = tid + u * 256;
        const int r = f >> 4, c = (f & 15) * 4;
        float4 t = *(const float4*)(Qb + (size_t)r * HDm + c);
        qs[r*AP + c + 0] = t.x * 0.125f;
        qs[r*AP + c + 1] = t.y * 0.125f;
        qs[r*AP + c + 2] = t.z * 0.125f;
        qs[r*AP + c + 3] = t.w * 0.125f;
    }

    float m_[4], l_[4], o_[4][4];
#pragma unroll
    for (int i = 0; i < 4; i++) {
        m_[i] = -1e30f; l_[i] = 0.f;
#pragma unroll
        for (int j = 0; j < 4; j++) o_[i][j] = 0.f;
    }

    for (int kv0 = 0; kv0 < Sq; kv0 += 64) {
        __syncthreads();   // prev tile fully consumed (incl. first-iter Q stores)
        // load K (transposed into kst) and V
#pragma unroll
        for (int u = 0; u < 4; u++) {
            const int f = tid + u * 256;
            const int r = f >> 4, c = (f & 15) * 4;
            float4 t = *(const float4*)(Kb + (size_t)(kv0 + r) * HDm + c);
            kst[(c+0)*AP + r] = t.x;
            kst[(c+1)*AP + r] = t.y;
            kst[(c+2)*AP + r] = t.z;
            kst[(c+3)*AP + r] = t.w;
            float4 w = *(const float4*)(Vb + (size_t)(kv0 + r) * HDm + c);
            *(float4*)&vs[r*AP + c] = w;
        }
        __syncthreads();

        // S = (Q*scale) @ K^T   (4x4 per thread, rows ty*4+i, cols tx*4+j)
        float s_[4][4];
#pragma unroll
        for (int i = 0; i < 4; i++)
#pragma unroll
            for (int j = 0; j < 4; j++) s_[i][j] = 0.f;

#pragma unroll
        for (int h4 = 0; h4 < 16; h4++) {
            float qv[4][4];
#pragma unroll
            for (int i = 0; i < 4; i++) {
                float4 t = *(float4*)&qs[(ty*4 + i)*AP + h4*4];
                qv[i][0] = t.x; qv[i][1] = t.y; qv[i][2] = t.z; qv[i][3] = t.w;
            }
#pragma unroll
            for (int w = 0; w < 4; w++) {
                float4 kk = *(float4*)&kst[(h4*4 + w)*AP + tx*4];
#pragma unroll
                for (int i = 0; i < 4; i++) {
                    s_[i][0] += qv[i][w] * kk.x;
                    s_[i][1] += qv[i][w] * kk.y;
                    s_[i][2] += qv[i][w] * kk.z;
                    s_[i][3] += qv[i][w] * kk.w;
                }
            }
        }

        // online softmax update
#pragma unroll
        for (int i = 0; i < 4; i++) {
            float tm = fmaxf(fmaxf(s_[i][0], s_[i][1]), fmaxf(s_[i][2], s_[i][3]));
#pragma unroll
            for (int off = 8; off >= 1; off >>= 1)
                tm = fmaxf(tm, __shfl_xor_sync(0xffffffffu, tm, off));
            const float mn   = fmaxf(m_[i], tm);
            const float corr = __expf(m_[i] - mn);
            float sum = 0.f;
#pragma unroll
            for (int j = 0; j < 4; j++) { s_[i][j] = __expf(s_[i][j] - mn); sum += s_[i][j]; }
#pragma unroll
            for (int off = 8; off >= 1; off >>= 1)
                sum += __shfl_xor_sync(0xffffffffu, sum, off);
            l_[i] = l_[i] * corr + sum;
            m_[i] = mn;
#pragma unroll
            for (int j = 0; j < 4; j++) o_[i][j] *= corr;
            *(float4*)&ps[(ty*4 + i)*AP + tx*4] =
                make_float4(s_[i][0], s_[i][1], s_[i][2], s_[i][3]);
        }
        __syncthreads();

        // O += P @ V
#pragma unroll
        for (int k4 = 0; k4 < 16; k4++) {
            float pv[4][4];
#pragma unroll
            for (int i = 0; i < 4; i++) {
                float4 t = *(float4*)&ps[(ty*4 + i)*AP + k4*4];
                pv[i][0] = t.x; pv[i][1] = t.y; pv[i][2] = t.z; pv[i][3] = t.w;
            }
#pragma unroll
            for (int w = 0; w < 4; w++) {
                float4 vv = *(float4*)&vs[(k4*4 + w)*AP + tx*4];
#pragma unroll
                for (int i = 0; i < 4; i++) {
                    o_[i][0] += pv[i][w] * vv.x;
                    o_[i][1] += pv[i][w] * vv.y;
                    o_[i][2] += pv[i][w] * vv.z;
                    o_[i][3] += pv[i][w] * vv.w;
                }
            }
        }
    }

    // normalize + write back token-major [B, S, D]
    const int b = bh >> 4, h = bh & 15;
#pragma unroll
    for (int i = 0; i < 4; i++) {
        const float inv = 1.f / l_[i];
        const int s = q0 + ty*4 + i;
        float4 o = make_float4(o_[i][0]*inv, o_[i][1]*inv, o_[i][2]*inv, o_[i][3]*inv);
        *(float4*)(Og + ((size_t)(b * Sq + s) * Dm + h * HDm + tx * 4)) = o;
    }
}

// ---------------------------------------------------------------------------
extern "C" void kernel_launch(void* const* d_in, const int* in_sizes, int n_in,
                              void* d_out, int out_size)
{
    const float* x    = (const float*)d_in[0];
    const float* Wq   = (const float*)d_in[1];
    const float* bq   = (const float*)d_in[2];
    const float* Wk   = (const float*)d_in[3];
    const float* bk   = (const float*)d_in[4];
    const float* Wv   = (const float*)d_in[5];
    const float* bv   = (const float*)d_in[6];
    const float* Wo   = (const float*)d_in[7];
    const float* bo   = (const float*)d_in[8];
    const float* ln1g = (const float*)d_in[9];
    const float* ln1b = (const float*)d_in[10];
    const float* ln2g = (const float*)d_in[11];
    const float* ln2b = (const float*)d_in[12];
    const float* W1   = (const float*)d_in[13];
    const float* b1   = (const float*)d_in[14];
    const float* W2   = (const float*)d_in[15];
    const float* b2   = (const float*)d_in[16];
    float* out = (float*)d_out;

    float *xn, *q, *k, *v, *att, *x2, *hb;
    cudaGetSymbolAddress((void**)&xn,  g_xn);
    cudaGetSymbolAddress((void**)&q,   g_q);
    cudaGetSymbolAddress((void**)&k,   g_k);
    cudaGetSymbolAddress((void**)&v,   g_v);
    cudaGetSymbolAddress((void**)&att, g_att);
    cudaGetSymbolAddress((void**)&x2,  g_x2);
    cudaGetSymbolAddress((void**)&hb,  g_h);

    cudaFuncSetAttribute(attn_kernel, cudaFuncAttributeMaxDynamicSharedMemorySize, ATT_SMEM);

    const dim3 blk(256);
    const dim3 gD (Dm  / 128, NTOK / 128);   // (8, 64)
    const dim3 gDF(DFm / 128, NTOK / 128);   // (32, 64)

    // 1) LN1
    ln_kernel<<<NTOK, blk>>>(x, ln1g, ln1b, xn);
    // 2) Q/K/V projections, scattered to [B,H,S,HD]
    sgemm_kernel<3><<<gD, blk>>>(xn, Wq, bq, nullptr, q, Dm, Dm);
    sgemm_kernel<3><<<gD, blk>>>(xn, Wk, bk, nullptr, k, Dm, Dm);
    sgemm_kernel<3><<<gD, blk>>>(xn, Wv, bv, nullptr, v, Dm, Dm);
    // 3) attention -> [B,S,D]
    attn_kernel<<<dim3(Sq / 64, Bq * Hh), blk, ATT_SMEM>>>(q, k, v, att);
    // 4) output projection + residual -> x2
    sgemm_kernel<2><<<gD, blk>>>(att, Wo, bo, x, x2, Dm, Dm);
    // 5) LN2 (reuse xn)
    ln_kernel<<<NTOK, blk>>>(x2, ln2g, ln2b, xn);
    // 6) FFN up + exact GELU
    sgemm_kernel<1><<<gDF, blk>>>(xn, W1, b1, nullptr, hb, DFm, Dm);
    // 7) FFN down + residual -> out
    sgemm_kernel<2><<<gD, blk>>>(hb, W2, b2, x2, out, Dm, DFm);
}

// round 6
// speedup vs baseline: 1.9636x; 1.9636x over previous
#include <cuda_runtime.h>
#include <cuda_bf16.h>
#include <math.h>
#include <stdint.h>

// Problem constants
#define Bq   4
#define Sq   2048
#define Dm   1024
#define Hh   16
#define HDm  64
#define DFm  4096
#define NTOK (Bq*Sq)   // 8192

// ---------------------------------------------------------------------------
// Scratch (module-load allocated)
// ---------------------------------------------------------------------------
__device__ float g_q  [NTOK*Dm];
__device__ float g_k  [NTOK*Dm];
__device__ float g_v  [NTOK*Dm];
__device__ float g_x2 [NTOK*Dm];

__device__ __nv_bfloat16 g_ahi[NTOK*Dm];
__device__ __nv_bfloat16 g_alo[NTOK*Dm];
__device__ __nv_bfloat16 g_hhi[NTOK*DFm];
__device__ __nv_bfloat16 g_hlo[NTOK*DFm];

__device__ __nv_bfloat16 g_wqh[Dm*Dm],  g_wql[Dm*Dm];
__device__ __nv_bfloat16 g_wkh[Dm*Dm],  g_wkl[Dm*Dm];
__device__ __nv_bfloat16 g_wvh[Dm*Dm],  g_wvl[Dm*Dm];
__device__ __nv_bfloat16 g_woh[Dm*Dm],  g_wol[Dm*Dm];
__device__ __nv_bfloat16 g_w1h[Dm*DFm], g_w1l[Dm*DFm];
__device__ __nv_bfloat16 g_w2h[Dm*DFm], g_w2l[Dm*DFm];

// ---------------------------------------------------------------------------
// PTX helpers (base-target safe: cp.async + ldmatrix + mma.sync only)
// ---------------------------------------------------------------------------
__device__ __forceinline__ uint32_t s2u(const void* p) {
    uint32_t a;
    asm("{ .reg .u64 t; cvta.to.shared.u64 t, %1; cvt.u32.u64 %0, t; }"
        : "=r"(a) : "l"(p));
    return a;
}
__device__ __forceinline__ void cpa16(uint32_t d, const void* s) {
    asm volatile("cp.async.cg.shared.global [%0], [%1], 16;"
                 :: "r"(d), "l"(s) : "memory");
}
__device__ __forceinline__ void cpa_commit() {
    asm volatile("cp.async.commit_group;" ::: "memory");
}
template<int NN> __device__ __forceinline__ void cpa_wait() {
    asm volatile("cp.async.wait_group %0;" :: "n"(NN) : "memory");
}
__device__ __forceinline__ void ldsm4(uint32_t* r, uint32_t a) {
    asm volatile("ldmatrix.sync.aligned.m8n8.x4.shared.b16 {%0,%1,%2,%3}, [%4];"
                 : "=r"(r[0]), "=r"(r[1]), "=r"(r[2]), "=r"(r[3]) : "r"(a));
}
__device__ __forceinline__ void ldsm2(uint32_t* r, uint32_t a) {
    asm volatile("ldmatrix.sync.aligned.m8n8.x2.shared.b16 {%0,%1}, [%2];"
                 : "=r"(r[0]), "=r"(r[1]) : "r"(a));
}
__device__ __forceinline__ void mma_bf16(float* d, const uint32_t* a, const uint32_t* b) {
    asm volatile(
        "mma.sync.aligned.m16n8k16.row.col.f32.bf16.bf16.f32 "
        "{%0,%1,%2,%3}, {%4,%5,%6,%7}, {%8,%9}, {%0,%1,%2,%3};"
        : "+f"(d[0]), "+f"(d[1]), "+f"(d[2]), "+f"(d[3])
        : "r"(a[0]), "r"(a[1]), "r"(a[2]), "r"(a[3]), "r"(b[0]), "r"(b[1]));
}

// split fp32 pairs/quads into bf16 hi/lo
__device__ __forceinline__ void split_store2(float x, float y,
                                             __nv_bfloat16* hi, __nv_bfloat16* lo) {
    __nv_bfloat16 hx = __float2bfloat16(x), hy = __float2bfloat16(y);
    float lx = x - __bfloat162float(hx), ly = y - __bfloat162float(hy);
    __nv_bfloat16 gx = __float2bfloat16(lx), gy = __float2bfloat16(ly);
    uint32_t H = (uint32_t)__bfloat16_as_ushort(hx) | ((uint32_t)__bfloat16_as_ushort(hy) << 16);
    uint32_t L = (uint32_t)__bfloat16_as_ushort(gx) | ((uint32_t)__bfloat16_as_ushort(gy) << 16);
    *(uint32_t*)hi = H;
    *(uint32_t*)lo = L;
}
__device__ __forceinline__ void split_store4(float4 v, __nv_bfloat16* hi, __nv_bfloat16* lo) {
    split_store2(v.x, v.y, hi,     lo);
    split_store2(v.z, v.w, hi + 2, lo + 2);
}

// ---------------------------------------------------------------------------
// LayerNorm: one block per row, emits bf16 hi/lo split directly
// ---------------------------------------------------------------------------
__global__ __launch_bounds__(256)
void ln_kernel(const float* __restrict__ X, const float* __restrict__ G,
               const float* __restrict__ Bt,
               __nv_bfloat16* __restrict__ Yhi, __nv_bfloat16* __restrict__ Ylo)
{
    __shared__ float ss[8], sq[8];
    const int r = blockIdx.x, tid = threadIdx.x;
    const float* xr = X + (size_t)r * Dm;
    float4 v = *(const float4*)(xr + tid * 4);
    float s = v.x + v.y + v.z + v.w;
    float q = v.x*v.x + v.y*v.y + v.z*v.z + v.w*v.w;
#pragma unroll
    for (int off = 16; off >= 1; off >>= 1) {
        s += __shfl_xor_sync(0xffffffffu, s, off);
        q += __shfl_xor_sync(0xffffffffu, q, off);
    }
    if ((tid & 31) == 0) { ss[tid >> 5] = s; sq[tid >> 5] = q; }
    __syncthreads();
    float ts = 0.f, tq = 0.f;
#pragma unroll
    for (int w = 0; w < 8; w++) { ts += ss[w]; tq += sq[w]; }
    const float mu   = ts * (1.0f / Dm);
    const float var  = tq * (1.0f / Dm) - mu * mu;
    const float rstd = rsqrtf(var + 1e-5f);
    float4 g4 = *(const float4*)(G  + tid * 4);
    float4 b4 = *(const float4*)(Bt + tid * 4);
    float4 o;
    o.x = (v.x - mu) * rstd * g4.x + b4.x;
    o.y = (v.y - mu) * rstd * g4.y + b4.y;
    o.z = (v.z - mu) * rstd * g4.z + b4.z;
    o.w = (v.w - mu) * rstd * g4.w + b4.w;
    const size_t idx = (size_t)r * Dm + tid * 4;
    split_store4(o, Yhi + idx, Ylo + idx);
}

// ---------------------------------------------------------------------------
// Weight convert+transpose: W[K,N] f32 -> WT hi/lo [N,K] bf16
// ---------------------------------------------------------------------------
__global__ __launch_bounds__(256)
void wconv_kernel(const float* __restrict__ W, __nv_bfloat16* __restrict__ Th,
                  __nv_bfloat16* __restrict__ Tl, int K, int N)
{
    __shared__ float t[32][33];
    const int n0 = blockIdx.x * 32, k0 = blockIdx.y * 32;
    const int tx = threadIdx.x, ty = threadIdx.y;
#pragma unroll
    for (int i = 0; i < 4; i++)
        t[ty + i*8][tx] = W[(size_t)(k0 + ty + i*8) * N + n0 + tx];
    __syncthreads();
#pragma unroll
    for (int i = 0; i < 4; i++) {
        const int r = ty + i*8;
        float v = t[tx][r];                     // = W[k0+tx][n0+r]
        size_t o = (size_t)(n0 + r) * K + k0 + tx;
        __nv_bfloat16 h = __float2bfloat16(v);
        Th[o] = h;
        Tl[o] = __float2bfloat16(v - __bfloat162float(h));
    }
}

// ---------------------------------------------------------------------------
// HMMA split-bf16 GEMM: C[M,N] = A[M,K] @ W[K,N] + bias (+epilogue)
//   A = (Ahi,Alo) [M,K] bf16 row-major; W = (Bhi,Blo) [N,K] bf16 (K-major).
//   D = Ah*Bh + Ah*Bl + Al*Bh in fp32 via mma.sync.m16n8k16.
// CTA tile 128x128, K-chunk 64 (128B rows, SW128), 3-stage cp.async.
// 8 warps as 2(M)x4(N); warp tile 64x32.
// MODE: 1 = bias+GELU -> bf16 hi/lo, 2 = bias+residual -> f32,
//       3 = bias -> f32 scatter to [B,H,S,HD]
// ---------------------------------------------------------------------------
#define TMq 128
#define TNq 128
#define TKq 64
#define TILE_B   16384               // one operand tile (128 x 128B)
#define STG_BYTES (4*TILE_B)         // Ah, Al, Bh, Bl
#define GEMM_SMEM (3*STG_BYTES)      // 196608
#define SWZ(x) ((x) ^ (((x) >> 3) & 0x70))

__device__ __forceinline__ void load_stage(
    uint32_t st,
    const __nv_bfloat16* __restrict__ Ahi, const __nv_bfloat16* __restrict__ Alo,
    const __nv_bfloat16* __restrict__ Bhi, const __nv_bfloat16* __restrict__ Blo,
    int m0, int n0, int kc, int K, int tid)
{
#pragma unroll
    for (int j = 0; j < 4; j++) {          // 128 rows x 8 chunks of 16B
        const int i = tid + j * 256;
        const int r = i >> 3, c = i & 7;
        const uint32_t off = SWZ((uint32_t)(r * 128 + c * 16));
        const size_t ga = (size_t)(m0 + r) * K + kc + c * 8;
        const size_t gb = (size_t)(n0 + r) * K + kc + c * 8;
        cpa16(st + off,              Ahi + ga);
        cpa16(st + TILE_B   + off,   Alo + ga);
        cpa16(st + 2*TILE_B + off,   Bhi + gb);
        cpa16(st + 3*TILE_B + off,   Blo + gb);
    }
}

template<int MODE>
__global__ __launch_bounds__(256, 1)
void gemm_hmma(const __nv_bfloat16* __restrict__ Ahi, const __nv_bfloat16* __restrict__ Alo,
               const __nv_bfloat16* __restrict__ Bhi, const __nv_bfloat16* __restrict__ Blo,
               const float* __restrict__ bias, const float* __restrict__ res,
               float* __restrict__ Cf,
               __nv_bfloat16* __restrict__ Chi, __nv_bfloat16* __restrict__ Clo,
               int N, int K)
{
    extern __shared__ __align__(1024) char smem[];
    const uint32_t sb = s2u(smem);
    const int tid = threadIdx.x, lane = tid & 31, warp = tid >> 5;
    const int wm = warp >> 2, wn = warp & 3;       // 2 x 4 warp grid
    const int m0 = blockIdx.y * TMq, n0 = blockIdx.x * TNq;

    float acc[4][4][4];
#pragma unroll
    for (int a = 0; a < 4; a++)
#pragma unroll
        for (int b = 0; b < 4; b++)
#pragma unroll
            for (int c = 0; c < 4; c++) acc[a][b][c] = 0.f;

    // per-thread ldmatrix row-byte offsets (swizzle folds in per-ks XOR)
    uint32_t rowA[4], rowB[4];
#pragma unroll
    for (int mf = 0; mf < 4; mf++)
        rowA[mf] = (uint32_t)((wm*64 + mf*16 + (lane & 15)) * 128 + (lane >> 4) * 16);
#pragma unroll
    for (int nf = 0; nf < 4; nf++)
        rowB[nf] = (uint32_t)((wn*32 + nf*8 + (lane & 7)) * 128 + ((lane >> 3) & 1) * 16);

    const int NC = K >> 6;
    // prologue: 3 stages
    load_stage(sb,               Ahi, Alo, Bhi, Blo, m0, n0, 0,   K, tid); cpa_commit();
    load_stage(sb +   STG_BYTES, Ahi, Alo, Bhi, Blo, m0, n0, 64,  K, tid); cpa_commit();
    load_stage(sb + 2*STG_BYTES, Ahi, Alo, Bhi, Blo, m0, n0, 128, K, tid); cpa_commit();

    int stg = 0;
    for (int c = 0; c < NC; c++) {
        const int rem = NC - 1 - c;
        if (rem >= 2)      cpa_wait<2>();
        else if (rem == 1) cpa_wait<1>();
        else               cpa_wait<0>();
        __syncthreads();

        const uint32_t stA = sb + stg * STG_BYTES;
#pragma unroll
        for (int ks = 0; ks < 4; ks++) {
            const uint32_t ko = ks * 32;
            uint32_t ah[4][4], al[4][4], bh[4][2], bl[4][2];
#pragma unroll
            for (int mf = 0; mf < 4; mf++) {
                const uint32_t so = SWZ(rowA[mf] + ko);
                ldsm4(ah[mf], stA + so);
                ldsm4(al[mf], stA + TILE_B + so);
            }
#pragma unroll
            for (int nf = 0; nf < 4; nf++) {
                const uint32_t so = SWZ(rowB[nf] + ko);
                ldsm2(bh[nf], stA + 2*TILE_B + so);
                ldsm2(bl[nf], stA + 3*TILE_B + so);
            }
#pragma unroll
            for (int mf = 0; mf < 4; mf++)
#pragma unroll
                for (int nf = 0; nf < 4; nf++) {
                    mma_bf16(acc[mf][nf], ah[mf], bh[nf]);
                    mma_bf16(acc[mf][nf], ah[mf], bl[nf]);
                    mma_bf16(acc[mf][nf], al[mf], bh[nf]);
                }
        }
        __syncthreads();
        if (c + 3 < NC) {
            load_stage(stA, Ahi, Alo, Bhi, Blo, m0, n0, (c + 3) * 64, K, tid);
            cpa_commit();
        }
        stg = (stg + 1 == 3) ? 0 : stg + 1;
    }

    // epilogue: thread holds (row, col) and (row+8, col), 2 floats each
    const int qr = lane >> 2, qc = (lane & 3) * 2;
#pragma unroll
    for (int mf = 0; mf < 4; mf++) {
#pragma unroll
        for (int nf = 0; nf < 4; nf++) {
            const int row = m0 + wm*64 + mf*16 + qr;
            const int col = n0 + wn*32 + nf*8 + qc;
            float2 bv = *(const float2*)(bias + col);
            float x0 = acc[mf][nf][0] + bv.x, x1 = acc[mf][nf][1] + bv.y;
            float y0 = acc[mf][nf][2] + bv.x, y1 = acc[mf][nf][3] + bv.y;
            if (MODE == 1) {
                x0 *= normcdff(x0); x1 *= normcdff(x1);
                y0 *= normcdff(y0); y1 *= normcdff(y1);
                const size_t o0 = (size_t)row * N + col;
                const size_t o1 = (size_t)(row + 8) * N + col;
                split_store2(x0, x1, Chi + o0, Clo + o0);
                split_store2(y0, y1, Chi + o1, Clo + o1);
            } else if (MODE == 2) {
                const size_t o0 = (size_t)row * N + col;
                const size_t o1 = (size_t)(row + 8) * N + col;
                float2 r0 = *(const float2*)(res + o0);
                float2 r1 = *(const float2*)(res + o1);
                *(float2*)(Cf + o0) = make_float2(x0 + r0.x, x1 + r0.y);
                *(float2*)(Cf + o1) = make_float2(y0 + r1.x, y1 + r1.y);
            } else {
                const int h = col >> 6, hd = col & 63;
                const int b0r = row >> 11, s0 = row & 2047;
                const int b1r = (row + 8) >> 11, s1 = (row + 8) & 2047;
                *(float2*)(Cf + (((size_t)(b0r * Hh + h) * Sq + s0) * HDm + hd)) =
                    make_float2(x0, x1);
                *(float2*)(Cf + (((size_t)(b1r * Hh + h) * Sq + s1) * HDm + hd)) =
                    make_float2(y0, y1);
            }
        }
    }
}

// ---------------------------------------------------------------------------
// Flash attention, fp32, output emitted as bf16 hi/lo split
// ---------------------------------------------------------------------------
#define AP 68
#define ATT_SMEM (4 * 64 * AP * 4)

__global__ __launch_bounds__(256, 2)
void attn_kernel(const float* __restrict__ Qg, const float* __restrict__ Kg,
                 const float* __restrict__ Vg,
                 __nv_bfloat16* __restrict__ Ohi, __nv_bfloat16* __restrict__ Olo)
{
    extern __shared__ float sm[];
    float* qs  = sm;
    float* kst = sm + 64*AP;
    float* vs  = sm + 2*64*AP;
    float* ps  = sm + 3*64*AP;

    const int tid = threadIdx.x;
    const int tx = tid & 15, ty = tid >> 4;
    const int bh = blockIdx.y;
    const int q0 = blockIdx.x * 64;
    const float* Qb = Qg + ((size_t)bh * Sq + q0) * HDm;
    const float* Kb = Kg + (size_t)bh * Sq * HDm;
    const float* Vb = Vg + (size_t)bh * Sq * HDm;

#pragma unroll
    for (int u = 0; u < 4; u++) {
        const int f = tid + u * 256;
        const int r = f >> 4, c = (f & 15) * 4;
        float4 t = *(const float4*)(Qb + (size_t)r * HDm + c);
        qs[r*AP + c + 0] = t.x * 0.125f;
        qs[r*AP + c + 1] = t.y * 0.125f;
        qs[r*AP + c + 2] = t.z * 0.125f;
        qs[r*AP + c + 3] = t.w * 0.125f;
    }

    float m_[4], l_[4], o_[4][4];
#pragma unroll
    for (int i = 0; i < 4; i++) {
        m_[i] = -1e30f; l_[i] = 0.f;
#pragma unroll
        for (int j = 0; j < 4; j++) o_[i][j] = 0.f;
    }

    for (int kv0 = 0; kv0 < Sq; kv0 += 64) {
        __syncthreads();
#pragma unroll
        for (int u = 0; u < 4; u++) {
            const int f = tid + u * 256;
            const int r = f >> 4, c = (f & 15) * 4;
            float4 t = *(const float4*)(Kb + (size_t)(kv0 + r) * HDm + c);
            kst[(c+0)*AP + r] = t.x;
            kst[(c+1)*AP + r] = t.y;
            kst[(c+2)*AP + r] = t.z;
            kst[(c+3)*AP + r] = t.w;
            float4 w = *(const float4*)(Vb + (size_t)(kv0 + r) * HDm + c);
            *(float4*)&vs[r*AP + c] = w;
        }
        __syncthreads();

        float s_[4][4];
#pragma unroll
        for (int i = 0; i < 4; i++)
#pragma unroll
            for (int j = 0; j < 4; j++) s_[i][j] = 0.f;

#pragma unroll
        for (int h4 = 0; h4 < 16; h4++) {
            float qv[4][4];
#pragma unroll
            for (int i = 0; i < 4; i++) {
                float4 t = *(float4*)&qs[(ty*4 + i)*AP + h4*4];
                qv[i][0] = t.x; qv[i][1] = t.y; qv[i][2] = t.z; qv[i][3] = t.w;
            }
#pragma unroll
            for (int w = 0; w < 4; w++) {
                float4 kk = *(float4*)&kst[(h4*4 + w)*AP + tx*4];
#pragma unroll
                for (int i = 0; i < 4; i++) {
                    s_[i][0] += qv[i][w] * kk.x;
                    s_[i][1] += qv[i][w] * kk.y;
                    s_[i][2] += qv[i][w] * kk.z;
                    s_[i][3] += qv[i][w] * kk.w;
                }
            }
        }

#pragma unroll
        for (int i = 0; i < 4; i++) {
            float tm = fmaxf(fmaxf(s_[i][0], s_[i][1]), fmaxf(s_[i][2], s_[i][3]));
#pragma unroll
            for (int off = 8; off >= 1; off >>= 1)
                tm = fmaxf(tm, __shfl_xor_sync(0xffffffffu, tm, off));
            const float mn   = fmaxf(m_[i], tm);
            const float corr = __expf(m_[i] - mn);
            float sum = 0.f;
#pragma unroll
            for (int j = 0; j < 4; j++) { s_[i][j] = __expf(s_[i][j] - mn); sum += s_[i][j]; }
#pragma unroll
            for (int off = 8; off >= 1; off >>= 1)
                sum += __shfl_xor_sync(0xffffffffu, sum, off);
            l_[i] = l_[i] * corr + sum;
            m_[i] = mn;
#pragma unroll
            for (int j = 0; j < 4; j++) o_[i][j] *= corr;
            *(float4*)&ps[(ty*4 + i)*AP + tx*4] =
                make_float4(s_[i][0], s_[i][1], s_[i][2], s_[i][3]);
        }
        __syncthreads();

#pragma unroll
        for (int k4 = 0; k4 < 16; k4++) {
            float pv[4][4];
#pragma unroll
            for (int i = 0; i < 4; i++) {
                float4 t = *(float4*)&ps[(ty*4 + i)*AP + k4*4];
                pv[i][0] = t.x; pv[i][1] = t.y; pv[i][2] = t.z; pv[i][3] = t.w;
            }
#pragma unroll
            for (int w = 0; w < 4; w++) {
                float4 vv = *(float4*)&vs[(k4*4 + w)*AP + tx*4];
#pragma unroll
                for (int i = 0; i < 4; i++) {
                    o_[i][0] += pv[i][w] * vv.x;
                    o_[i][1] += pv[i][w] * vv.y;
                    o_[i][2] += pv[i][w] * vv.z;
                    o_[i][3] += pv[i][w] * vv.w;
                }
            }
        }
    }

    const int b = bh >> 4, h = bh & 15;
#pragma unroll
    for (int i = 0; i < 4; i++) {
        const float inv = 1.f / l_[i];
        const int s = q0 + ty*4 + i;
        float4 o = make_float4(o_[i][0]*inv, o_[i][1]*inv, o_[i][2]*inv, o_[i][3]*inv);
        const size_t base = ((size_t)(b * Sq + s) * Dm + h * HDm + tx * 4);
        split_store4(o, Ohi + base, Olo + base);
    }
}

// ---------------------------------------------------------------------------
extern "C" void kernel_launch(void* const* d_in, const int* in_sizes, int n_in,
                              void* d_out, int out_size)
{
    const float* x    = (const float*)d_in[0];
    const float* Wq   = (const float*)d_in[1];
    const float* bq   = (const float*)d_in[2];
    const float* Wk   = (const float*)d_in[3];
    const float* bk   = (const float*)d_in[4];
    const float* Wv   = (const float*)d_in[5];
    const float* bv   = (const float*)d_in[6];
    const float* Wo   = (const float*)d_in[7];
    const float* bo   = (const float*)d_in[8];
    const float* ln1g = (const float*)d_in[9];
    const float* ln1b = (const float*)d_in[10];
    const float* ln2g = (const float*)d_in[11];
    const float* ln2b = (const float*)d_in[12];
    const float* W1   = (const float*)d_in[13];
    const float* b1   = (const float*)d_in[14];
    const float* W2   = (const float*)d_in[15];
    const float* b2   = (const float*)d_in[16];
    float* out = (float*)d_out;

    float *q, *k, *v, *x2;
    __nv_bfloat16 *ahi, *alo, *hhi, *hlo;
    __nv_bfloat16 *wqh, *wql, *wkh, *wkl, *wvh, *wvl, *woh, *wol, *w1h, *w1l, *w2h, *w2l;
    cudaGetSymbolAddress((void**)&q,   g_q);
    cudaGetSymbolAddress((void**)&k,   g_k);
    cudaGetSymbolAddress((void**)&v,   g_v);
    cudaGetSymbolAddress((void**)&x2,  g_x2);
    cudaGetSymbolAddress((void**)&ahi, g_ahi);
    cudaGetSymbolAddress((void**)&alo, g_alo);
    cudaGetSymbolAddress((void**)&hhi, g_hhi);
    cudaGetSymbolAddress((void**)&hlo, g_hlo);
    cudaGetSymbolAddress((void**)&wqh, g_wqh); cudaGetSymbolAddress((void**)&wql, g_wql);
    cudaGetSymbolAddress((void**)&wkh, g_wkh); cudaGetSymbolAddress((void**)&wkl, g_wkl);
    cudaGetSymbolAddress((void**)&wvh, g_wvh); cudaGetSymbolAddress((void**)&wvl, g_wvl);
    cudaGetSymbolAddress((void**)&woh, g_woh); cudaGetSymbolAddress((void**)&wol, g_wol);
    cudaGetSymbolAddress((void**)&w1h, g_w1h); cudaGetSymbolAddress((void**)&w1l, g_w1l);
    cudaGetSymbolAddress((void**)&w2h, g_w2h); cudaGetSymbolAddress((void**)&w2l, g_w2l);

    cudaFuncSetAttribute(attn_kernel, cudaFuncAttributeMaxDynamicSharedMemorySize, ATT_SMEM);
    cudaFuncSetAttribute(gemm_hmma<1>, cudaFuncAttributeMaxDynamicSharedMemorySize, GEMM_SMEM);
    cudaFuncSetAttribute(gemm_hmma<2>, cudaFuncAttributeMaxDynamicSharedMemorySize, GEMM_SMEM);
    cudaFuncSetAttribute(gemm_hmma<3>, cudaFuncAttributeMaxDynamicSharedMemorySize, GEMM_SMEM);

    const dim3 blk(256);
    const dim3 wblk(32, 8);
    const dim3 gP (Dm  / TNq, NTOK / TMq);   // (8, 64)
    const dim3 gF1(DFm / TNq, NTOK / TMq);   // (32, 64)

    // 0) weight convert + transpose (hi/lo bf16, [N,K])
    wconv_kernel<<<dim3(Dm/32,  Dm/32),  wblk>>>(Wq, wqh, wql, Dm,  Dm);
    wconv_kernel<<<dim3(Dm/32,  Dm/32),  wblk>>>(Wk, wkh, wkl, Dm,  Dm);
    wconv_kernel<<<dim3(Dm/32,  Dm/32),  wblk>>>(Wv, wvh, wvl, Dm,  Dm);
    wconv_kernel<<<dim3(Dm/32,  Dm/32),  wblk>>>(Wo, woh, wol, Dm,  Dm);
    wconv_kernel<<<dim3(DFm/32, Dm/32),  wblk>>>(W1, w1h, w1l, Dm,  DFm);
    wconv_kernel<<<dim3(Dm/32,  DFm/32), wblk>>>(W2, w2h, w2l, DFm, Dm);

    // 1) LN1 -> bf16 split
    ln_kernel<<<NTOK, blk>>>(x, ln1g, ln1b, ahi, alo);
    // 2) Q/K/V projections (HMMA), scattered to [B,H,S,HD] f32
    gemm_hmma<3><<<gP, blk, GEMM_SMEM>>>(ahi, alo, wqh, wql, bq, nullptr, q, nullptr, nullptr, Dm, Dm);
    gemm_hmma<3><<<gP, blk, GEMM_SMEM>>>(ahi, alo, wkh, wkl, bk, nullptr, k, nullptr, nullptr, Dm, Dm);
    gemm_hmma<3><<<gP, blk, GEMM_SMEM>>>(ahi, alo, wvh, wvl, bv, nullptr, v, nullptr, nullptr, Dm, Dm);
    // 3) attention -> bf16 split [B,S,D]
    attn_kernel<<<dim3(Sq / 64, Bq * Hh), blk, ATT_SMEM>>>(q, k, v, ahi, alo);
    // 4) output projection + residual -> x2 (f32)
    gemm_hmma<2><<<gP, blk, GEMM_SMEM>>>(ahi, alo, woh, wol, bo, x, x2, nullptr, nullptr, Dm, Dm);
    // 5) LN2 -> bf16 split
    ln_kernel<<<NTOK, blk>>>(x2, ln2g, ln2b, ahi, alo);
    // 6) FFN up + exact GELU -> bf16 split h
    gemm_hmma<1><<<gF1, blk, GEMM_SMEM>>>(ahi, alo, w1h, w1l, b1, nullptr, nullptr, hhi, hlo, DFm, Dm);
    // 7) FFN down + residual -> out (f32)
    gemm_hmma<2><<<gP, blk, GEMM_SMEM>>>(hhi, hlo, w2h, w2l, b2, x2, out, nullptr, nullptr, Dm, DFm);
}

// round 7
// speedup vs baseline: 3.1628x; 1.6107x over previous
#include <cuda_runtime.h>
#include <cuda_bf16.h>
#include <math.h>
#include <stdint.h>

// Problem constants
#define Bq   4
#define Sq   2048
#define Dm   1024
#define Hh   16
#define HDm  64
#define DFm  4096
#define NTOK (Bq*Sq)   // 8192
#define QKV_SZ (NTOK*Dm)   // = BH * S * 64

// ---------------------------------------------------------------------------
// Scratch (module-load allocated)
// ---------------------------------------------------------------------------
__device__ float g_x2 [NTOK*Dm];

__device__ __nv_bfloat16 g_ahi[NTOK*Dm];
__device__ __nv_bfloat16 g_alo[NTOK*Dm];
__device__ __nv_bfloat16 g_hhi[NTOK*DFm];
__device__ __nv_bfloat16 g_hlo[NTOK*DFm];

__device__ __nv_bfloat16 g_qh[QKV_SZ], g_ql[QKV_SZ];
__device__ __nv_bfloat16 g_kh[QKV_SZ], g_kl[QKV_SZ];
__device__ __nv_bfloat16 g_vh[QKV_SZ], g_vl[QKV_SZ];

__device__ __nv_bfloat16 g_wqh[Dm*Dm],  g_wql[Dm*Dm];
__device__ __nv_bfloat16 g_wkh[Dm*Dm],  g_wkl[Dm*Dm];
__device__ __nv_bfloat16 g_wvh[Dm*Dm],  g_wvl[Dm*Dm];
__device__ __nv_bfloat16 g_woh[Dm*Dm],  g_wol[Dm*Dm];
__device__ __nv_bfloat16 g_w1h[Dm*DFm], g_w1l[Dm*DFm];
__device__ __nv_bfloat16 g_w2h[Dm*DFm], g_w2l[Dm*DFm];

// ---------------------------------------------------------------------------
// PTX helpers (base-target safe: cp.async + ldmatrix + mma.sync only)
// ---------------------------------------------------------------------------
__device__ __forceinline__ uint32_t s2u(const void* p) {
    uint32_t a;
    asm("{ .reg .u64 t; cvta.to.shared.u64 t, %1; cvt.u32.u64 %0, t; }"
        : "=r"(a) : "l"(p));
    return a;
}
__device__ __forceinline__ void cpa16(uint32_t d, const void* s) {
    asm volatile("cp.async.cg.shared.global [%0], [%1], 16;"
                 :: "r"(d), "l"(s) : "memory");
}
__device__ __forceinline__ void cpa_commit() {
    asm volatile("cp.async.commit_group;" ::: "memory");
}
template<int NN> __device__ __forceinline__ void cpa_wait() {
    asm volatile("cp.async.wait_group %0;" :: "n"(NN) : "memory");
}
__device__ __forceinline__ void ldsm4(uint32_t* r, uint32_t a) {
    asm volatile("ldmatrix.sync.aligned.m8n8.x4.shared.b16 {%0,%1,%2,%3}, [%4];"
                 : "=r"(r[0]), "=r"(r[1]), "=r"(r[2]), "=r"(r[3]) : "r"(a));
}
__device__ __forceinline__ void ldsm4t(uint32_t* r, uint32_t a) {
    asm volatile("ldmatrix.sync.aligned.m8n8.x4.trans.shared.b16 {%0,%1,%2,%3}, [%4];"
                 : "=r"(r[0]), "=r"(r[1]), "=r"(r[2]), "=r"(r[3]) : "r"(a));
}
__device__ __forceinline__ void ldsm2(uint32_t* r, uint32_t a) {
    asm volatile("ldmatrix.sync.aligned.m8n8.x2.shared.b16 {%0,%1}, [%2];"
                 : "=r"(r[0]), "=r"(r[1]) : "r"(a));
}
__device__ __forceinline__ void mma_bf16(float* d, const uint32_t* a, const uint32_t* b) {
    asm volatile(
        "mma.sync.aligned.m16n8k16.row.col.f32.bf16.bf16.f32 "
        "{%0,%1,%2,%3}, {%4,%5,%6,%7}, {%8,%9}, {%0,%1,%2,%3};"
        : "+f"(d[0]), "+f"(d[1]), "+f"(d[2]), "+f"(d[3])
        : "r"(a[0]), "r"(a[1]), "r"(a[2]), "r"(a[3]), "r"(b[0]), "r"(b[1]));
}

// split fp32 pairs into bf16 hi/lo
__device__ __forceinline__ void split_pack2(float x, float y, uint32_t& H, uint32_t& L) {
    __nv_bfloat16 hx = __float2bfloat16(x), hy = __float2bfloat16(y);
    float lx = x - __bfloat162float(hx), ly = y - __bfloat162float(hy);
    __nv_bfloat16 gx = __float2bfloat16(lx), gy = __float2bfloat16(ly);
    H = (uint32_t)__bfloat16_as_ushort(hx) | ((uint32_t)__bfloat16_as_ushort(hy) << 16);
    L = (uint32_t)__bfloat16_as_ushort(gx) | ((uint32_t)__bfloat16_as_ushort(gy) << 16);
}
__device__ __forceinline__ void split_store2(float x, float y,
                                             __nv_bfloat16* hi, __nv_bfloat16* lo) {
    uint32_t H, L;
    split_pack2(x, y, H, L);
    *(uint32_t*)hi = H;
    *(uint32_t*)lo = L;
}
__device__ __forceinline__ void split_store4(float4 v, __nv_bfloat16* hi, __nv_bfloat16* lo) {
    split_store2(v.x, v.y, hi,     lo);
    split_store2(v.z, v.w, hi + 2, lo + 2);
}

#define SWZ(x) ((x) ^ (((x) >> 3) & 0x70))

// ---------------------------------------------------------------------------
// LayerNorm: one block per row, emits bf16 hi/lo split directly
// ---------------------------------------------------------------------------
__global__ __launch_bounds__(256)
void ln_kernel(const float* __restrict__ X, const float* __restrict__ G,
               const float* __restrict__ Bt,
               __nv_bfloat16* __restrict__ Yhi, __nv_bfloat16* __restrict__ Ylo)
{
    __shared__ float ss[8], sq[8];
    const int r = blockIdx.x, tid = threadIdx.x;
    const float* xr = X + (size_t)r * Dm;
    float4 v = *(const float4*)(xr + tid * 4);
    float s = v.x + v.y + v.z + v.w;
    float q = v.x*v.x + v.y*v.y + v.z*v.z + v.w*v.w;
#pragma unroll
    for (int off = 16; off >= 1; off >>= 1) {
        s += __shfl_xor_sync(0xffffffffu, s, off);
        q += __shfl_xor_sync(0xffffffffu, q, off);
    }
    if ((tid & 31) == 0) { ss[tid >> 5] = s; sq[tid >> 5] = q; }
    __syncthreads();
    float ts = 0.f, tq = 0.f;
#pragma unroll
    for (int w = 0; w < 8; w++) { ts += ss[w]; tq += sq[w]; }
    const float mu   = ts * (1.0f / Dm);
    const float var  = tq * (1.0f / Dm) - mu * mu;
    const float rstd = rsqrtf(var + 1e-5f);
    float4 g4 = *(const float4*)(G  + tid * 4);
    float4 b4 = *(const float4*)(Bt + tid * 4);
    float4 o;
    o.x = (v.x - mu) * rstd * g4.x + b4.x;
    o.y = (v.y - mu) * rstd * g4.y + b4.y;
    o.z = (v.z - mu) * rstd * g4.z + b4.z;
    o.w = (v.w - mu) * rstd * g4.w + b4.w;
    const size_t idx = (size_t)r * Dm + tid * 4;
    split_store4(o, Yhi + idx, Ylo + idx);
}

// ---------------------------------------------------------------------------
// Weight convert+transpose: W[K,N] f32 -> WT hi/lo [N,K] bf16
// ---------------------------------------------------------------------------
__global__ __launch_bounds__(256)
void wconv_kernel(const float* __restrict__ W, __nv_bfloat16* __restrict__ Th,
                  __nv_bfloat16* __restrict__ Tl, int K, int N)
{
    __shared__ float t[32][33];
    const int n0 = blockIdx.x * 32, k0 = blockIdx.y * 32;
    const int tx = threadIdx.x, ty = threadIdx.y;
#pragma unroll
    for (int i = 0; i < 4; i++)
        t[ty + i*8][tx] = W[(size_t)(k0 + ty + i*8) * N + n0 + tx];
    __syncthreads();
#pragma unroll
    for (int i = 0; i < 4; i++) {
        const int r = ty + i*8;
        float v = t[tx][r];                     // = W[k0+tx][n0+r]
        size_t o = (size_t)(n0 + r) * K + k0 + tx;
        __nv_bfloat16 h = __float2bfloat16(v);
        Th[o] = h;
        Tl[o] = __float2bfloat16(v - __bfloat162float(h));
    }
}

// ---------------------------------------------------------------------------
// HMMA split-bf16 GEMM (as R6). MODE 3 now writes bf16 hi/lo scattered QKV.
// ---------------------------------------------------------------------------
#define TMq 128
#define TNq 128
#define TILE_B   16384
#define STG_BYTES (4*TILE_B)
#define GEMM_SMEM (3*STG_BYTES)

__device__ __forceinline__ void load_stage(
    uint32_t st,
    const __nv_bfloat16* __restrict__ Ahi, const __nv_bfloat16* __restrict__ Alo,
    const __nv_bfloat16* __restrict__ Bhi, const __nv_bfloat16* __restrict__ Blo,
    int m0, int n0, int kc, int K, int tid)
{
#pragma unroll
    for (int j = 0; j < 4; j++) {
        const int i = tid + j * 256;
        const int r = i >> 3, c = i & 7;
        const uint32_t off = SWZ((uint32_t)(r * 128 + c * 16));
        const size_t ga = (size_t)(m0 + r) * K + kc + c * 8;
        const size_t gb = (size_t)(n0 + r) * K + kc + c * 8;
        cpa16(st + off,              Ahi + ga);
        cpa16(st + TILE_B   + off,   Alo + ga);
        cpa16(st + 2*TILE_B + off,   Bhi + gb);
        cpa16(st + 3*TILE_B + off,   Blo + gb);
    }
}

template<int MODE>
__global__ __launch_bounds__(256, 1)
void gemm_hmma(const __nv_bfloat16* __restrict__ Ahi, const __nv_bfloat16* __restrict__ Alo,
               const __nv_bfloat16* __restrict__ Bhi, const __nv_bfloat16* __restrict__ Blo,
               const float* __restrict__ bias, const float* __restrict__ res,
               float* __restrict__ Cf,
               __nv_bfloat16* __restrict__ Chi, __nv_bfloat16* __restrict__ Clo,
               int N, int K)
{
    extern __shared__ __align__(1024) char smem[];
    const uint32_t sb = s2u(smem);
    const int tid = threadIdx.x, lane = tid & 31, warp = tid >> 5;
    const int wm = warp >> 2, wn = warp & 3;
    const int m0 = blockIdx.y * TMq, n0 = blockIdx.x * TNq;

    float acc[4][4][4];
#pragma unroll
    for (int a = 0; a < 4; a++)
#pragma unroll
        for (int b = 0; b < 4; b++)
#pragma unroll
            for (int c = 0; c < 4; c++) acc[a][b][c] = 0.f;

    uint32_t rowA[4], rowB[4];
#pragma unroll
    for (int mf = 0; mf < 4; mf++)
        rowA[mf] = (uint32_t)((wm*64 + mf*16 + (lane & 15)) * 128 + (lane >> 4) * 16);
#pragma unroll
    for (int nf = 0; nf < 4; nf++)
        rowB[nf] = (uint32_t)((wn*32 + nf*8 + (lane & 7)) * 128 + ((lane >> 3) & 1) * 16);

    const int NC = K >> 6;
    load_stage(sb,               Ahi, Alo, Bhi, Blo, m0, n0, 0,   K, tid); cpa_commit();
    load_stage(sb +   STG_BYTES, Ahi, Alo, Bhi, Blo, m0, n0, 64,  K, tid); cpa_commit();
    load_stage(sb + 2*STG_BYTES, Ahi, Alo, Bhi, Blo, m0, n0, 128, K, tid); cpa_commit();

    int stg = 0;
    for (int c = 0; c < NC; c++) {
        const int rem = NC - 1 - c;
        if (rem >= 2)      cpa_wait<2>();
        else if (rem == 1) cpa_wait<1>();
        else               cpa_wait<0>();
        __syncthreads();

        const uint32_t stA = sb + stg * STG_BYTES;
#pragma unroll
        for (int ks = 0; ks < 4; ks++) {
            const uint32_t ko = ks * 32;
            uint32_t ah[4][4], al[4][4], bh[4][2], bl[4][2];
#pragma unroll
            for (int mf = 0; mf < 4; mf++) {
                const uint32_t so = SWZ(rowA[mf] + ko);
                ldsm4(ah[mf], stA + so);
                ldsm4(al[mf], stA + TILE_B + so);
            }
#pragma unroll
            for (int nf = 0; nf < 4; nf++) {
                const uint32_t so = SWZ(rowB[nf] + ko);
                ldsm2(bh[nf], stA + 2*TILE_B + so);
                ldsm2(bl[nf], stA + 3*TILE_B + so);
            }
#pragma unroll
            for (int mf = 0; mf < 4; mf++)
#pragma unroll
                for (int nf = 0; nf < 4; nf++) {
                    mma_bf16(acc[mf][nf], ah[mf], bh[nf]);
                    mma_bf16(acc[mf][nf], ah[mf], bl[nf]);
                    mma_bf16(acc[mf][nf], al[mf], bh[nf]);
                }
        }
        __syncthreads();
        if (c + 3 < NC) {
            load_stage(stA, Ahi, Alo, Bhi, Blo, m0, n0, (c + 3) * 64, K, tid);
            cpa_commit();
        }
        stg = (stg + 1 == 3) ? 0 : stg + 1;
    }

    const int qr = lane >> 2, qc = (lane & 3) * 2;
#pragma unroll
    for (int mf = 0; mf < 4; mf++) {
#pragma unroll
        for (int nf = 0; nf < 4; nf++) {
            const int row = m0 + wm*64 + mf*16 + qr;
            const int col = n0 + wn*32 + nf*8 + qc;
            float2 bv = *(const float2*)(bias + col);
            float x0 = acc[mf][nf][0] + bv.x, x1 = acc[mf][nf][1] + bv.y;
            float y0 = acc[mf][nf][2] + bv.x, y1 = acc[mf][nf][3] + bv.y;
            if (MODE == 1) {
                x0 *= normcdff(x0); x1 *= normcdff(x1);
                y0 *= normcdff(y0); y1 *= normcdff(y1);
                const size_t o0 = (size_t)row * N + col;
                const size_t o1 = (size_t)(row + 8) * N + col;
                split_store2(x0, x1, Chi + o0, Clo + o0);
                split_store2(y0, y1, Chi + o1, Clo + o1);
            } else if (MODE == 2) {
                const size_t o0 = (size_t)row * N + col;
                const size_t o1 = (size_t)(row + 8) * N + col;
                float2 r0 = *(const float2*)(res + o0);
                float2 r1 = *(const float2*)(res + o1);
                *(float2*)(Cf + o0) = make_float2(x0 + r0.x, x1 + r0.y);
                *(float2*)(Cf + o1) = make_float2(y0 + r1.x, y1 + r1.y);
            } else {
                // scatter to [B,H,S,64] as bf16 hi/lo
                const int h = col >> 6, hd = col & 63;
                const int b0r = row >> 11, s0 = row & 2047;
                const int b1r = (row + 8) >> 11, s1 = (row + 8) & 2047;
                const size_t o0 = ((size_t)(b0r * Hh + h) * Sq + s0) * HDm + hd;
                const size_t o1 = ((size_t)(b1r * Hh + h) * Sq + s1) * HDm + hd;
                split_store2(x0, x1, Chi + o0, Clo + o0);
                split_store2(y0, y1, Chi + o1, Clo + o1);
            }
        }
    }
}

// ---------------------------------------------------------------------------
// HMMA flash attention with split-bf16 QK^T and PV.
// CTA: 128 queries x one (b,h); 8 warps, warp = 16 query rows.
// KV tiles of 64 keys; K,V hi/lo in a 3-stage cp.async pipeline.
// Q/K/V: bf16 [BH, S, 64] (128B rows). Output: bf16 hi/lo [B,S,D] token-major.
// ---------------------------------------------------------------------------
#define ATT_QB   16384                    // one Q tensor tile (128 x 128B)
#define ATT_KVB  8192                     // one KV tensor tile (64 x 128B)
#define ATT_STG  (4*ATT_KVB)              // kh, kl, vh, vl
#define ATT_SMEM (2*ATT_QB + 3*ATT_STG)   // 131072

__device__ __forceinline__ void att_load_stage(
    uint32_t st, const __nv_bfloat16* __restrict__ Kh, const __nv_bfloat16* __restrict__ Kl,
    const __nv_bfloat16* __restrict__ Vh, const __nv_bfloat16* __restrict__ Vl,
    size_t tb, int kv0, int tid)
{
#pragma unroll
    for (int j = 0; j < 8; j++) {
        const int i = tid + j * 256;           // 0..2047
        const int t = i >> 9;                  // 0..3 : kh,kl,vh,vl
        const int r = (i >> 3) & 63;
        const int c = i & 7;
        const __nv_bfloat16* src = (t == 0) ? Kh : (t == 1) ? Kl : (t == 2) ? Vh : Vl;
        cpa16(st + t * ATT_KVB + SWZ((uint32_t)(r * 128 + c * 16)),
              src + tb + (size_t)(kv0 + r) * HDm + c * 8);
    }
}

__global__ __launch_bounds__(256, 1)
void attn_hmma(const __nv_bfloat16* __restrict__ Qh_, const __nv_bfloat16* __restrict__ Ql_,
               const __nv_bfloat16* __restrict__ Kh_, const __nv_bfloat16* __restrict__ Kl_,
               const __nv_bfloat16* __restrict__ Vh_, const __nv_bfloat16* __restrict__ Vl_,
               __nv_bfloat16* __restrict__ Ohi, __nv_bfloat16* __restrict__ Olo)
{
    extern __shared__ __align__(1024) char smem[];
    const uint32_t sb = s2u(smem);
    const int tid = threadIdx.x, lane = tid & 31, warp = tid >> 5;
    const int bh = blockIdx.y;
    const int q0 = blockIdx.x * 128;
    const size_t tb = (size_t)bh * Sq * HDm;

    // prologue: 3 KV stages + Q
    att_load_stage(sb + 2*ATT_QB,             Kh_, Kl_, Vh_, Vl_, tb, 0,   tid); cpa_commit();
    att_load_stage(sb + 2*ATT_QB +   ATT_STG, Kh_, Kl_, Vh_, Vl_, tb, 64,  tid); cpa_commit();
    att_load_stage(sb + 2*ATT_QB + 2*ATT_STG, Kh_, Kl_, Vh_, Vl_, tb, 128, tid); cpa_commit();
#pragma unroll
    for (int j = 0; j < 8; j++) {
        const int i = tid + j * 256;           // 0..2047
        const int t = i >> 10;                 // 0..1 : qh, ql
        const int r = (i >> 3) & 127;
        const int c = i & 7;
        const __nv_bfloat16* src = t ? Ql_ : Qh_;
        cpa16(sb + t * ATT_QB + SWZ((uint32_t)(r * 128 + c * 16)),
              src + tb + (size_t)(q0 + r) * HDm + c * 8);
    }
    cpa_commit();
    cpa_wait<0>();
    __syncthreads();

    // Q fragments to registers (A operand, m16k16 per k-frag)
    uint32_t qfh[4][4], qfl[4][4];
    {
        const uint32_t qrow = (uint32_t)((16*warp + (lane & 15)) * 128 + (lane >> 4) * 16);
#pragma unroll
        for (int kf = 0; kf < 4; kf++) {
            const uint32_t so = SWZ(qrow + kf * 32);
            ldsm4(qfh[kf], sb + so);
            ldsm4(qfl[kf], sb + ATT_QB + so);
        }
    }

    float acco[8][4];
#pragma unroll
    for (int nf = 0; nf < 8; nf++)
#pragma unroll
        for (int c = 0; c < 4; c++) acco[nf][c] = 0.f;
    float m0v = -1e30f, m1v = -1e30f, l0v = 0.f, l1v = 0.f;

    const int NT = Sq / 64;   // 32
    int stg = 0;
    for (int c = 0; c < NT; c++) {
        const int rem = NT - 1 - c;
        if (rem >= 2)      cpa_wait<2>();
        else if (rem == 1) cpa_wait<1>();
        else               cpa_wait<0>();
        __syncthreads();

        const uint32_t stb = sb + 2*ATT_QB + stg * ATT_STG;

        // ---- S = Q K^T (3-way split), accs[nf] covers keys 8nf..8nf+7 ----
        float accs[8][4];
#pragma unroll
        for (int nf = 0; nf < 8; nf++)
#pragma unroll
            for (int q4 = 0; q4 < 4; q4++) accs[nf][q4] = 0.f;

#pragma unroll
        for (int kf = 0; kf < 4; kf++) {
            uint32_t bhf[4][4], blf[4][4];
#pragma unroll
            for (int nfp = 0; nfp < 4; nfp++) {
                const uint32_t row = (uint32_t)(16*nfp + ((lane >> 4) << 3) + (lane & 7));
                const uint32_t kb  = (uint32_t)(kf * 32 + ((lane >> 3) & 1) * 16);
                const uint32_t so  = SWZ(row * 128 + kb);
                ldsm4(bhf[nfp], stb + so);
                ldsm4(blf[nfp], stb + ATT_KVB + so);
            }
#pragma unroll
            for (int nfp = 0; nfp < 4; nfp++) {
                mma_bf16(accs[2*nfp],   qfh[kf], &bhf[nfp][0]);
                mma_bf16(accs[2*nfp],   qfh[kf], &blf[nfp][0]);
                mma_bf16(accs[2*nfp],   qfl[kf], &bhf[nfp][0]);
                mma_bf16(accs[2*nfp+1], qfh[kf], &bhf[nfp][2]);
                mma_bf16(accs[2*nfp+1], qfh[kf], &blf[nfp][2]);
                mma_bf16(accs[2*nfp+1], qfl[kf], &bhf[nfp][2]);
            }
        }

        // ---- online softmax (rows qr, qr+8; quad lanes share a row) ----
        float mx0 = -1e30f, mx1 = -1e30f;
#pragma unroll
        for (int nf = 0; nf < 8; nf++) {
            mx0 = fmaxf(mx0, fmaxf(accs[nf][0], accs[nf][1]));
            mx1 = fmaxf(mx1, fmaxf(accs[nf][2], accs[nf][3]));
        }
        mx0 *= 0.125f; mx1 *= 0.125f;
#pragma unroll
        for (int off = 1; off <= 2; off <<= 1) {
            mx0 = fmaxf(mx0, __shfl_xor_sync(0xffffffffu, mx0, off));
            mx1 = fmaxf(mx1, __shfl_xor_sync(0xffffffffu, mx1, off));
        }
        const float mn0 = fmaxf(m0v, mx0), mn1 = fmaxf(m1v, mx1);
        const float cr0 = __expf(m0v - mn0), cr1 = __expf(m1v - mn1);
        float sum0 = 0.f, sum1 = 0.f;
#pragma unroll
        for (int nf = 0; nf < 8; nf++) {
            float p0 = __expf(fmaf(accs[nf][0], 0.125f, -mn0));
            float p1 = __expf(fmaf(accs[nf][1], 0.125f, -mn0));
            float p2 = __expf(fmaf(accs[nf][2], 0.125f, -mn1));
            float p3 = __expf(fmaf(accs[nf][3], 0.125f, -mn1));
            accs[nf][0] = p0; accs[nf][1] = p1; accs[nf][2] = p2; accs[nf][3] = p3;
            sum0 += p0 + p1; sum1 += p2 + p3;
        }
#pragma unroll
        for (int off = 1; off <= 2; off <<= 1) {
            sum0 += __shfl_xor_sync(0xffffffffu, sum0, off);
            sum1 += __shfl_xor_sync(0xffffffffu, sum1, off);
        }
        l0v = l0v * cr0 + sum0;  m0v = mn0;
        l1v = l1v * cr1 + sum1;  m1v = mn1;
#pragma unroll
        for (int nf = 0; nf < 8; nf++) {
            acco[nf][0] *= cr0; acco[nf][1] *= cr0;
            acco[nf][2] *= cr1; acco[nf][3] *= cr1;
        }

        // ---- O += P V (3-way split); P frags from S accumulators ----
#pragma unroll
        for (int kf2 = 0; kf2 < 4; kf2++) {
            uint32_t aPh[4], aPl[4];
            split_pack2(accs[2*kf2][0],   accs[2*kf2][1],   aPh[0], aPl[0]);
            split_pack2(accs[2*kf2][2],   accs[2*kf2][3],   aPh[1], aPl[1]);
            split_pack2(accs[2*kf2+1][0], accs[2*kf2+1][1], aPh[2], aPl[2]);
            split_pack2(accs[2*kf2+1][2], accs[2*kf2+1][3], aPh[3], aPl[3]);
#pragma unroll
            for (int nfp2 = 0; nfp2 < 4; nfp2++) {
                const uint32_t row  = (uint32_t)(16*kf2 + ((lane >> 3) & 1) * 8 + (lane & 7));
                const uint32_t colb = (uint32_t)(nfp2 * 32 + (lane >> 4) * 16);
                const uint32_t so   = SWZ(row * 128 + colb);
                uint32_t vhf[4], vlf[4];
                ldsm4t(vhf, stb + 2*ATT_KVB + so);
                ldsm4t(vlf, stb + 3*ATT_KVB + so);
                mma_bf16(acco[2*nfp2],   aPh, &vhf[0]);
                mma_bf16(acco[2*nfp2],   aPh, &vlf[0]);
                mma_bf16(acco[2*nfp2],   aPl, &vhf[0]);
                mma_bf16(acco[2*nfp2+1], aPh, &vhf[2]);
                mma_bf16(acco[2*nfp2+1], aPh, &vlf[2]);
                mma_bf16(acco[2*nfp2+1], aPl, &vhf[2]);
            }
        }

        __syncthreads();
        if (c + 3 < NT) {
            att_load_stage(sb + 2*ATT_QB + stg * ATT_STG,
                           Kh_, Kl_, Vh_, Vl_, tb, (c + 3) * 64, tid);
            cpa_commit();
        }
        stg = (stg + 1 == 3) ? 0 : stg + 1;
    }

    // ---- normalize + write bf16 hi/lo to [B,S,D] token-major ----
    const float inv0 = 1.f / l0v, inv1 = 1.f / l1v;
    const int b = bh >> 4, h = bh & 15;
    const int s0 = q0 + warp * 16 + (lane >> 2), s1 = s0 + 8;
#pragma unroll
    for (int nf = 0; nf < 8; nf++) {
        const int col = h * HDm + nf * 8 + (lane & 3) * 2;
        const size_t o0 = (size_t)(b * Sq + s0) * Dm + col;
        const size_t o1 = (size_t)(b * Sq + s1) * Dm + col;
        split_store2(acco[nf][0] * inv0, acco[nf][1] * inv0, Ohi + o0, Olo + o0);
        split_store2(acco[nf][2] * inv1, acco[nf][3] * inv1, Ohi + o1, Olo + o1);
    }
}

// ---------------------------------------------------------------------------
extern "C" void kernel_launch(void* const* d_in, const int* in_sizes, int n_in,
                              void* d_out, int out_size)
{
    const float* x    = (const float*)d_in[0];
    const float* Wq   = (const float*)d_in[1];
    const float* bq   = (const float*)d_in[2];
    const float* Wk   = (const float*)d_in[3];
    const float* bk   = (const float*)d_in[4];
    const float* Wv   = (const float*)d_in[5];
    const float* bv   = (const float*)d_in[6];
    const float* Wo   = (const float*)d_in[7];
    const float* bo   = (const float*)d_in[8];
    const float* ln1g = (const float*)d_in[9];
    const float* ln1b = (const float*)d_in[10];
    const float* ln2g = (const float*)d_in[11];
    const float* ln2b = (const float*)d_in[12];
    const float* W1   = (const float*)d_in[13];
    const float* b1   = (const float*)d_in[14];
    const float* W2   = (const float*)d_in[15];
    const float* b2   = (const float*)d_in[16];
    float* out = (float*)d_out;

    float *x2;
    __nv_bfloat16 *ahi, *alo, *hhi, *hlo;
    __nv_bfloat16 *qh, *ql, *kh, *kl, *vh, *vl;
    __nv_bfloat16 *wqh, *wql, *wkh, *wkl, *wvh, *wvl, *woh, *wol, *w1h, *w1l, *w2h, *w2l;
    cudaGetSymbolAddress((void**)&x2,  g_x2);
    cudaGetSymbolAddress((void**)&ahi, g_ahi);
    cudaGetSymbolAddress((void**)&alo, g_alo);
    cudaGetSymbolAddress((void**)&hhi, g_hhi);
    cudaGetSymbolAddress((void**)&hlo, g_hlo);
    cudaGetSymbolAddress((void**)&qh,  g_qh); cudaGetSymbolAddress((void**)&ql, g_ql);
    cudaGetSymbolAddress((void**)&kh,  g_kh); cudaGetSymbolAddress((void**)&kl, g_kl);
    cudaGetSymbolAddress((void**)&vh,  g_vh); cudaGetSymbolAddress((void**)&vl, g_vl);
    cudaGetSymbolAddress((void**)&wqh, g_wqh); cudaGetSymbolAddress((void**)&wql, g_wql);
    cudaGetSymbolAddress((void**)&wkh, g_wkh); cudaGetSymbolAddress((void**)&wkl, g_wkl);
    cudaGetSymbolAddress((void**)&wvh, g_wvh); cudaGetSymbolAddress((void**)&wvl, g_wvl);
    cudaGetSymbolAddress((void**)&woh, g_woh); cudaGetSymbolAddress((void**)&wol, g_wol);
    cudaGetSymbolAddress((void**)&w1h, g_w1h); cudaGetSymbolAddress((void**)&w1l, g_w1l);
    cudaGetSymbolAddress((void**)&w2h, g_w2h); cudaGetSymbolAddress((void**)&w2l, g_w2l);

    cudaFuncSetAttribute(attn_hmma, cudaFuncAttributeMaxDynamicSharedMemorySize, ATT_SMEM);
    cudaFuncSetAttribute(gemm_hmma<1>, cudaFuncAttributeMaxDynamicSharedMemorySize, GEMM_SMEM);
    cudaFuncSetAttribute(gemm_hmma<2>, cudaFuncAttributeMaxDynamicSharedMemorySize, GEMM_SMEM);
    cudaFuncSetAttribute(gemm_hmma<3>, cudaFuncAttributeMaxDynamicSharedMemorySize, GEMM_SMEM);

    const dim3 blk(256);
    const dim3 wblk(32, 8);
    const dim3 gP (Dm  / TNq, NTOK / TMq);   // (8, 64)
    const dim3 gF1(DFm / TNq, NTOK / TMq);   // (32, 64)

    // 0) weight convert + transpose (hi/lo bf16, [N,K])
    wconv_kernel<<<dim3(Dm/32,  Dm/32),  wblk>>>(Wq, wqh, wql, Dm,  Dm);
    wconv_kernel<<<dim3(Dm/32,  Dm/32),  wblk>>>(Wk, wkh, wkl, Dm,  Dm);
    wconv_kernel<<<dim3(Dm/32,  Dm/32),  wblk>>>(Wv, wvh, wvl, Dm,  Dm);
    wconv_kernel<<<dim3(Dm/32,  Dm/32),  wblk>>>(Wo, woh, wol, Dm,  Dm);
    wconv_kernel<<<dim3(DFm/32, Dm/32),  wblk>>>(W1, w1h, w1l, Dm,  DFm);
    wconv_kernel<<<dim3(Dm/32,  DFm/32), wblk>>>(W2, w2h, w2l, DFm, Dm);

    // 1) LN1 -> bf16 split
    ln_kernel<<<NTOK, blk>>>(x, ln1g, ln1b, ahi, alo);
    // 2) Q/K/V projections (HMMA) -> bf16 hi/lo scattered [B,H,S,64]
    gemm_hmma<3><<<gP, blk, GEMM_SMEM>>>(ahi, alo, wqh, wql, bq, nullptr, nullptr, qh, ql, Dm, Dm);
    gemm_hmma<3><<<gP, blk, GEMM_SMEM>>>(ahi, alo, wkh, wkl, bk, nullptr, nullptr, kh, kl, Dm, Dm);
    gemm_hmma<3><<<gP, blk, GEMM_SMEM>>>(ahi, alo, wvh, wvl, bv, nullptr, nullptr, vh, vl, Dm, Dm);
    // 3) attention (HMMA) -> bf16 hi/lo [B,S,D]
    attn_hmma<<<dim3(Sq / 128, Bq * Hh), blk, ATT_SMEM>>>(qh, ql, kh, kl, vh, vl, ahi, alo);
    // 4) output projection + residual -> x2 (f32)
    gemm_hmma<2><<<gP, blk, GEMM_SMEM>>>(ahi, alo, woh, wol, bo, x, x2, nullptr, nullptr, Dm, Dm);
    // 5) LN2 -> bf16 split
    ln_kernel<<<NTOK, blk>>>(x2, ln2g, ln2b, ahi, alo);
    // 6) FFN up + exact GELU -> bf16 split h
    gemm_hmma<1><<<gF1, blk, GEMM_SMEM>>>(ahi, alo, w1h, w1l, b1, nullptr, nullptr, hhi, hlo, DFm, Dm);
    // 7) FFN down + residual -> out (f32)
    gemm_hmma<2><<<gP, blk, GEMM_SMEM>>>(hhi, hlo, w2h, w2l, b2, x2, out, nullptr, nullptr, Dm, DFm);
}